// round 5
// baseline (speedup 1.0000x reference)
#include <cuda_runtime.h>
#include <cstdint>

// ---------------------------------------------------------------------------
// TrilineVAE full pipeline (smem-tiled direct convs + packed f32x2 FMA)
// ---------------------------------------------------------------------------

#define PRED_SIZE 1769472   // 2*96^3
#define HALF_PRED 884736    // 96^3

typedef unsigned long long ull;

__device__ __forceinline__ ull fma2(ull a, ull b, ull c) {
    ull r;
    asm("fma.rn.f32x2 %0,%1,%2,%3;" : "=l"(r) : "l"(a), "l"(b), "l"(c));
    return r;
}
__device__ __forceinline__ ull mul2(ull a, ull b) {
    ull r;
    asm("mul.rn.f32x2 %0,%1,%2;" : "=l"(r) : "l"(a), "l"(b));
    return r;
}
__device__ __forceinline__ void unpack2(ull v, float& lo, float& hi) {
    asm("mov.b64 {%0,%1},%2;" : "=f"(lo), "=f"(hi) : "l"(v));
}

// ---------------- scratch (__device__ globals; no allocation) --------------
__device__ __align__(16) float g_act0[2 * 32 * 48 * 48 * 48];   // 7,077,888
__device__ __align__(16) float g_act1[2 * 64 * 24 * 24 * 24];   // 1,769,472
__device__ __align__(16) float g_act2raw[4 * 2 * 128 * 1728];   // 1,769,472
__device__ __align__(16) float g_act2[2 * 128 * 1728];          //   442,368
__device__ __align__(16) float g_act3raw[8 * 2 * 256 * 216];    //   884,736
__device__ __align__(16) float g_act3[2 * 256 * 216];           //   110,592
__device__ __align__(16) float g_act4raw[16 * 2 * 512 * 27];    //   442,368
__device__ __align__(16) float g_xpad5[2 * 512 * 64];           //    65,536
__device__ __align__(16) float g_flat5[2 * 512];
__device__ __align__(16) float g_z[2 * 128];
__device__ __align__(16) float g_knots[6 * 512];
__device__ __align__(16) float g_feats[2 * 3 * 512 * 32];       //    98,304
__device__ __align__(16) float g_g[2 * 3 * 96 * 32];            //    18,432

// ---------------------------------------------------------------------------
// Tiled direct conv3d (k=4, s=2, p=1), packed-f32x2 inner loop.
// Thread computes PT positions x OCT ocs; acc packed over (even,odd) kw taps.
// ---------------------------------------------------------------------------
template <int CIN, int COUT, int SIN, int SOUT, int TD, int TH, int TW,
          int OCB, int ICT, int ICSPLIT, int PT, int OCT, bool FUSE>
__global__ void convt_k(const float* __restrict__ in, const float* __restrict__ wt,
                        const float* __restrict__ bias, float* __restrict__ out) {
    constexpr int POS_TILE = TD * TH * TW;
    constexpr int NPOS_T = POS_TILE / PT;
    constexpr int NOC_T = OCB / OCT;
    constexpr int BLK = NPOS_T * NOC_T;
    constexpr int TD2 = 2 * TD + 2, TH2 = 2 * TH + 2, TW2 = 2 * TW + 2;
    constexpr int INEL = TD2 * TH2 * TW2;
    constexpr int POS_OUT = SOUT * SOUT * SOUT;
    constexpr int ICR = CIN / ICSPLIT;
    constexpr int NT_W = SOUT / TW, NT_H = SOUT / TH;

    __shared__ __align__(16) float sIn[ICT * INEL];
    __shared__ __align__(16) float sW[OCB * ICT * 64];

    const int tid = threadIdx.x;
    const int n = blockIdx.z;
    const int oc0 = blockIdx.y * OCB;
    int bx = blockIdx.x;
    const int sp = bx % ICSPLIT; bx /= ICSPLIT;
    const int twi = bx % NT_W; bx /= NT_W;
    const int thi = bx % NT_H; bx /= NT_H;
    const int tdi = bx;
    const int od0 = tdi * TD, oh0 = thi * TH, ow0 = twi * TW;
    const int id0 = 2 * od0 - 1, ih0 = 2 * oh0 - 1, iw0 = 2 * ow0 - 1;
    const int icBeg = sp * ICR;

    const int posT = tid % NPOS_T;
    const int ocT = tid / NPOS_T;

    int baseq[PT];
    int gpos[PT];
#pragma unroll
    for (int q = 0; q < PT; q++) {
        int p = posT + q * NPOS_T;
        int owl = p % TW;
        int ohl = (p / TW) % TH;
        int odl = p / (TW * TH);
        baseq[q] = (2 * odl) * TH2 * TW2 + (2 * ohl) * TW2 + 2 * owl;
        gpos[q] = ((od0 + odl) * SOUT + (oh0 + ohl)) * SOUT + (ow0 + owl);
    }

    ull acc2[PT * OCT];
#pragma unroll
    for (int i = 0; i < PT * OCT; i++) acc2[i] = 0ull;

    const float* inN = in + (size_t)n * CIN * SIN * SIN * SIN;

    for (int icc = 0; icc < ICR; icc += ICT) {
        __syncthreads();
        // stage input tile (with halo, zero-padded)
        for (int e = tid; e < ICT * INEL; e += BLK) {
            int icl = e / INEL;
            int r = e % INEL;
            int dd = r / (TH2 * TW2);
            int hh = (r / TW2) % TH2;
            int ww = r % TW2;
            int id = id0 + dd, ih = ih0 + hh, iw = iw0 + ww;
            float v = 0.f;
            if ((unsigned)id < (unsigned)SIN && (unsigned)ih < (unsigned)SIN &&
                (unsigned)iw < (unsigned)SIN)
                v = __ldg(&inN[(((size_t)(icBeg + icc + icl) * SIN + id) * SIN + ih) * SIN + iw]);
            sIn[e] = v;
        }
        // stage weight chunk
        for (int e = tid; e < OCB * ICT * 64; e += BLK) {
            int o = e / (ICT * 64);
            int r = e % (ICT * 64);
            int icl = r / 64;
            int t = r % 64;
            sW[e] = __ldg(&wt[((size_t)(oc0 + o) * CIN + (icBeg + icc + icl)) * 64 + t]);
        }
        __syncthreads();

#pragma unroll
        for (int icl = 0; icl < ICT; icl++) {
            const float* inL = sIn + icl * INEL;
#pragma unroll
            for (int kd = 0; kd < 4; kd++) {
#pragma unroll
                for (int kh = 0; kh < 4; kh++) {
                    const float* row = inL + kd * TH2 * TW2 + kh * TW2;
                    ull xu[PT][2];
#pragma unroll
                    for (int q = 0; q < PT; q++) {
                        const ull* rp = reinterpret_cast<const ull*>(row + baseq[q]);
                        xu[q][0] = rp[0];
                        xu[q][1] = rp[1];
                    }
#pragma unroll
                    for (int j = 0; j < OCT; j++) {
                        const ull* wp = reinterpret_cast<const ull*>(
                            sW + ((ocT * OCT + j) * ICT + icl) * 64 + kd * 16 + kh * 4);
                        ull w0 = wp[0], w1 = wp[1];
#pragma unroll
                        for (int q = 0; q < PT; q++) {
                            ull a = acc2[q * OCT + j];
                            a = fma2(xu[q][0], w0, a);
                            a = fma2(xu[q][1], w1, a);
                            acc2[q * OCT + j] = a;
                        }
                    }
                }
            }
        }
    }

    if (FUSE) {
#pragma unroll
        for (int j = 0; j < OCT; j++) {
            int oc = oc0 + ocT * OCT + j;
            float bb = __ldg(&bias[oc]);
#pragma unroll
            for (int q = 0; q < PT; q++) {
                float lo, hi;
                unpack2(acc2[q * OCT + j], lo, hi);
                out[((size_t)n * COUT + oc) * POS_OUT + gpos[q]] =
                    fmaxf(lo + hi + bb, 0.f);
            }
        }
    } else {
        float* outS = out + (size_t)sp * (2ull * COUT * POS_OUT);
#pragma unroll
        for (int j = 0; j < OCT; j++) {
            int oc = oc0 + ocT * OCT + j;
#pragma unroll
            for (int q = 0; q < PT; q++) {
                float lo, hi;
                unpack2(acc2[q * OCT + j], lo, hi);
                outS[((size_t)n * COUT + oc) * POS_OUT + gpos[q]] = lo + hi;
            }
        }
    }
}

// generic slice reducer: sum NS slices + bias + relu
template <int NS, int TOTAL, int PP, int COUT>
__global__ void reduceN_k(const float* __restrict__ raw, const float* __restrict__ bias,
                          float* __restrict__ out) {
    int idx = blockIdx.x * 256 + threadIdx.x;
    if (idx >= TOTAL) return;
    float s = __ldg(&bias[(idx / PP) % COUT]);
#pragma unroll
    for (int q = 0; q < NS; q++) s += raw[(size_t)q * TOTAL + idx];
    out[idx] = fmaxf(s, 0.f);
}

// reduce 16 IC-split slices of conv4, add bias, relu, scatter into the
// zero-padded im2col vector for conv5 (layout [n][ic][kd][kh][kw]).
__global__ void pad45_k(const float* __restrict__ b4) {
    int idx = blockIdx.x * 256 + threadIdx.x;  // < 65536
    int n = idx >> 15;
    int r = idx & 32767;
    int ic = r >> 6;
    int tt = r & 63;
    int kd = tt >> 4, kh = (tt >> 2) & 3, kw = tt & 3;
    float val = 0.f;
    if (kd >= 1 && kh >= 1 && kw >= 1) {
        int base = (n * 512 + ic) * 27 + (kd - 1) * 9 + (kh - 1) * 3 + (kw - 1);
        float s = __ldg(&b4[ic]);
#pragma unroll
        for (int q = 0; q < 16; q++) s += g_act4raw[q * 27648 + base];
        val = fmaxf(s, 0.f);
    }
    g_xpad5[idx] = val;
}

// conv5 as dot products: out[n,oc] = xpad[n] . W5[oc]  (K = 512*64 = 32768)
__global__ void conv5_k(const float* __restrict__ w5, const float* __restrict__ b5) {
    const int oc = blockIdx.x;
    const int t = threadIdx.x;
    const float* wr = w5 + (size_t)oc * 32768;
    ull a0 = 0ull, a1 = 0ull;
    for (int k = t * 4; k < 32768; k += 1024) {
        const ull* w = reinterpret_cast<const ull*>(wr + k);
        const ull* x0 = reinterpret_cast<const ull*>(g_xpad5 + k);
        const ull* x1 = reinterpret_cast<const ull*>(g_xpad5 + 32768 + k);
        ull w0 = w[0], w1 = w[1];
        a0 = fma2(w0, x0[0], a0); a0 = fma2(w1, x0[1], a0);
        a1 = fma2(w0, x1[0], a1); a1 = fma2(w1, x1[1], a1);
    }
    float l0, h0, l1, h1;
    unpack2(a0, l0, h0);
    unpack2(a1, l1, h1);
    float s0v = l0 + h0, s1v = l1 + h1;
    __shared__ float s0[8], s1[8];
    int lane = t & 31, wid = t >> 5;
#pragma unroll
    for (int off = 16; off; off >>= 1) {
        s0v += __shfl_down_sync(0xffffffffu, s0v, off);
        s1v += __shfl_down_sync(0xffffffffu, s1v, off);
    }
    if (lane == 0) { s0[wid] = s0v; s1[wid] = s1v; }
    __syncthreads();
    if (t == 0) {
        float r0 = 0.f, r1 = 0.f;
#pragma unroll
        for (int q = 0; q < 8; q++) { r0 += s0[q]; r1 += s1[q]; }
        float bb = __ldg(&b5[oc]);
        g_flat5[oc]       = fmaxf(r0 + bb, 0.f);
        g_flat5[512 + oc] = fmaxf(r1 + bb, 0.f);
    }
}

// fc -> stats -> mu/logvar -> z ; writes mu, logvar to d_out tail
__global__ void head1_k(const float* __restrict__ fc_w, const float* __restrict__ fc_b,
                        const float* __restrict__ eps, float* __restrict__ d_out) {
    __shared__ float fs[1024];
    __shared__ float stats[512];
    int t = threadIdx.x;  // 256
    for (int e = t; e < 1024; e += 256) fs[e] = g_flat5[e];
    __syncthreads();
    {
        float a0 = __ldg(&fc_b[t]), a1 = a0;
        for (int i = 0; i < 512; i++) {
            float w = __ldg(&fc_w[i * 256 + t]);
            a0 = fmaf(fs[i], w, a0);
            a1 = fmaf(fs[512 + i], w, a1);
        }
        stats[t] = a0;
        stats[256 + t] = a1;
    }
    __syncthreads();
    int n = t >> 7, jj = t & 127;
    float mu = stats[n * 256 + jj];
    float lv = stats[n * 256 + 128 + jj];
    g_z[t] = mu + __ldg(&eps[t]) * expf(0.5f * lv);
    d_out[PRED_SIZE + t] = mu;
    d_out[PRED_SIZE + 256 + t] = lv;
}

// feats = relu(z @ fl_w + fl_b) -> [2,3,512,32]; both batches per thread
__global__ void feats_k(const float* __restrict__ fl_w, const float* __restrict__ fl_b) {
    __shared__ float zs[256];
    int t = threadIdx.x;
    int gid = blockIdx.x * 256 + t;  // < 49152
    zs[t] = g_z[t];
    __syncthreads();
    float b = __ldg(&fl_b[gid]);
    float a0 = b, a1 = b;
#pragma unroll 4
    for (int i = 0; i < 128; i++) {
        float w = __ldg(&fl_w[(size_t)i * 49152 + gid]);
        a0 = fmaf(zs[i], w, a0);
        a1 = fmaf(zs[128 + i], w, a1);
    }
    g_feats[gid] = fmaxf(a0, 0.f);
    g_feats[49152 + gid] = fmaxf(a1, 0.f);
}

// deltas row -> softmax -> cumsum -> knots  (one block per (b,axis))
__global__ void deltas_k(const float* __restrict__ dl_w, const float* __restrict__ dl_b) {
    int b = blockIdx.x / 3, ax = blockIdx.x % 3;
    int t = threadIdx.x;  // 512
    __shared__ float zs[128];
    __shared__ float v[512];
    __shared__ float r[512];
    if (t < 128) zs[t] = g_z[b * 128 + t];
    __syncthreads();
    float val = -1e30f;
    if (t < 511) {
        float a = __ldg(&dl_b[ax * 511 + t]);
        for (int i = 0; i < 128; i++)
            a = fmaf(zs[i], __ldg(&dl_w[i * 1533 + ax * 511 + t]), a);
        val = a;
    }
    r[t] = val;
    __syncthreads();
    for (int s = 256; s > 0; s >>= 1) {
        if (t < s) r[t] = fmaxf(r[t], r[t + s]);
        __syncthreads();
    }
    float mx = r[0];
    __syncthreads();
    float e = (t < 511) ? expf(val - mx) : 0.f;
    r[t] = e;
    __syncthreads();
    for (int s = 256; s > 0; s >>= 1) {
        if (t < s) r[t] += r[t + s];
        __syncthreads();
    }
    float sum = r[0];
    __syncthreads();
    v[t] = e / sum;
    __syncthreads();
    for (int off = 1; off < 512; off <<= 1) {
        float x = v[t];
        float add = (t >= off) ? v[t - off] : 0.f;
        __syncthreads();
        v[t] = x + add;
        __syncthreads();
    }
    float* kr = g_knots + (b * 3 + ax) * 512;
    if (t == 0) kr[0] = 0.f;
    if (t < 511) kr[t + 1] = v[t];
}

// Separable triline table: one block (32 threads) per (b,axis,i).
__global__ void gtable_k() {
    int blk = blockIdx.x;  // 576
    int i = blk % 96;
    int ax = (blk / 96) % 3;
    int b = blk / 288;
    const float* kr = g_knots + (b * 3 + ax) * 512;
    float u = (i + 0.5f) * (1.0f / 96.0f);
    int lo = 0, hi = 512;
    while (lo < hi) {
        int mid = (lo + hi) >> 1;
        if (__ldg(&kr[mid]) <= u) lo = mid + 1; else hi = mid;
    }
    int idx = lo - 1;
    idx = max(0, min(idx, 510));
    float t0 = __ldg(&kr[idx]), t1 = __ldg(&kr[idx + 1]);
    float w = (u - t0) / (t1 - t0 + 1e-8f);
    w = fminf(fmaxf(w, 0.f), 1.f);
    int d = threadIdx.x;
    const float* fr = g_feats + (((b * 3 + ax) * 512) + idx) * 32;
    g_g[((b * 3 + ax) * 96 + i) * 32 + d] = fr[d] * (1.f - w) + fr[32 + d] * w;
}

// Decoder: f = g0[i]*g1[j]*g2[k]; h = relu(f@W1+b1); logit = h@w2+b2.
// Packed f32x2 over feature-dim pairs; both batches per thread.
__global__ __launch_bounds__(256) void decoder_k(
    const float* __restrict__ w1, const float* __restrict__ b1,
    const float* __restrict__ w2, const float* __restrict__ b2,
    float* __restrict__ out) {
    __shared__ __align__(16) float W1t[64 * 32];  // transposed: W1t[k][j]
    __shared__ float b1s[64], w2s[64];
    int t = threadIdx.x;
    for (int e = t; e < 2048; e += 256) {
        int k = e >> 5, j = e & 31;
        W1t[e] = __ldg(&w1[j * 64 + k]);
    }
    if (t < 64) { b1s[t] = __ldg(&b1[t]); w2s[t] = __ldg(&w2[t]); }
    __syncthreads();

    int p = blockIdx.x * 256 + t;
    int k = p % 96;
    int ij = p / 96;
    int j = ij % 96;
    int i = ij / 96;

    const ull* a0 = reinterpret_cast<const ull*>(g_g + (0 * 96 + i) * 32);
    const ull* a1 = reinterpret_cast<const ull*>(g_g + (1 * 96 + j) * 32);
    const ull* a2 = reinterpret_cast<const ull*>(g_g + (2 * 96 + k) * 32);
    const ull* c0 = reinterpret_cast<const ull*>(g_g + 9216 + (0 * 96 + i) * 32);
    const ull* c1 = reinterpret_cast<const ull*>(g_g + 9216 + (1 * 96 + j) * 32);
    const ull* c2 = reinterpret_cast<const ull*>(g_g + 9216 + (2 * 96 + k) * 32);

    ull fa[16], fb[16];
#pragma unroll
    for (int q = 0; q < 16; q++) {
        fa[q] = mul2(mul2(__ldg(a0 + q), __ldg(a1 + q)), __ldg(a2 + q));
        fb[q] = mul2(mul2(__ldg(c0 + q), __ldg(c1 + q)), __ldg(c2 + q));
    }

    float bv = __ldg(b2);
    float la = bv, lb = bv;
#pragma unroll 2
    for (int kk = 0; kk < 64; kk++) {
        const ull* wp = reinterpret_cast<const ull*>(W1t + kk * 32);
        ull accA = 0ull, accB = 0ull;
#pragma unroll
        for (int q = 0; q < 16; q++) {
            ull w = wp[q];
            accA = fma2(fa[q], w, accA);
            accB = fma2(fb[q], w, accB);
        }
        float l0, h0, l1, h1;
        unpack2(accA, l0, h0);
        unpack2(accB, l1, h1);
        la = fmaf(fmaxf(l0 + h0 + b1s[kk], 0.f), w2s[kk], la);
        lb = fmaf(fmaxf(l1 + h1 + b1s[kk], 0.f), w2s[kk], lb);
    }
    out[p] = la;
    out[HALF_PRED + p] = lb;
}

// ---------------------------------------------------------------------------
extern "C" void kernel_launch(void* const* d_in, const int* in_sizes, int n_in,
                              void* d_out, int out_size) {
    const float* occ  = (const float*)d_in[0];
    const float* eps  = (const float*)d_in[1];
    const float* cw0  = (const float*)d_in[3];
    const float* cb0  = (const float*)d_in[4];
    const float* cw1  = (const float*)d_in[5];
    const float* cb1  = (const float*)d_in[6];
    const float* cw2  = (const float*)d_in[7];
    const float* cb2  = (const float*)d_in[8];
    const float* cw3  = (const float*)d_in[9];
    const float* cb3  = (const float*)d_in[10];
    const float* cw4  = (const float*)d_in[11];
    const float* cb4  = (const float*)d_in[12];
    const float* cw5  = (const float*)d_in[13];
    const float* cb5  = (const float*)d_in[14];
    const float* fc_w = (const float*)d_in[15];
    const float* fc_b = (const float*)d_in[16];
    const float* dl_w = (const float*)d_in[17];
    const float* dl_b = (const float*)d_in[18];
    const float* fl_w = (const float*)d_in[19];
    const float* fl_b = (const float*)d_in[20];
    const float* w1   = (const float*)d_in[21];
    const float* b1   = (const float*)d_in[22];
    const float* w2   = (const float*)d_in[23];
    const float* b2   = (const float*)d_in[24];
    float* out = (float*)d_out;

    float *a0p, *a1p, *a2rp, *a2p, *a3rp, *a3p, *a4rp;
    cudaGetSymbolAddress((void**)&a0p, g_act0);
    cudaGetSymbolAddress((void**)&a1p, g_act1);
    cudaGetSymbolAddress((void**)&a2rp, g_act2raw);
    cudaGetSymbolAddress((void**)&a2p, g_act2);
    cudaGetSymbolAddress((void**)&a3rp, g_act3raw);
    cudaGetSymbolAddress((void**)&a3p, g_act3);
    cudaGetSymbolAddress((void**)&a4rp, g_act4raw);

    // conv0: 1->32, 96->48, tile 8x8x8, OCB16, fused
    convt_k<1, 32, 96, 48, 8, 8, 8, 16, 1, 1, 4, 8, true>
        <<<dim3(216, 2, 2), 256>>>(occ, cw0, cb0, a0p);
    // conv1: 32->64, 48->24, tile 4x8x8, OCB16, ICT2, fused
    convt_k<32, 64, 48, 24, 4, 8, 8, 16, 2, 1, 4, 8, true>
        <<<dim3(54, 4, 2), 128>>>(a0p, cw1, cb1, a1p);
    // conv2: 64->128, 24->12, tile 6x6x12, OCB16, ICSPLIT4
    convt_k<64, 128, 24, 12, 6, 6, 12, 16, 1, 4, 4, 8, false>
        <<<dim3(16, 8, 2), 216>>>(a1p, cw2, cb2, a2rp);
    reduceN_k<4, 442368, 1728, 128><<<1728, 256>>>(a2rp, cb2, a2p);
    // conv3: 128->256, 12->6, tile 6x6x6, OCB32, ICT2, ICSPLIT8
    convt_k<128, 256, 12, 6, 6, 6, 6, 32, 2, 8, 4, 8, false>
        <<<dim3(8, 8, 2), 216>>>(a2p, cw3, cb3, a3rp);
    reduceN_k<8, 110592, 216, 256><<<432, 256>>>(a3rp, cb3, a3p);
    // conv4: 256->512, 6->3, tile 3x3x3, OCB32, ICT4, ICSPLIT16
    convt_k<256, 512, 6, 3, 3, 3, 3, 32, 4, 16, 1, 8, false>
        <<<dim3(16, 16, 2), 108>>>(a3p, cw4, cb4, a4rp);
    pad45_k<<<256, 256>>>(cb4);
    // conv5: 512->512, 3->1 (padded dot-product)
    conv5_k<<<512, 256>>>(cw5, cb5);
    // fc / reparam / mu,logvar out
    head1_k<<<1, 256>>>(fc_w, fc_b, eps, out);
    // feature lines + knots
    feats_k<<<192, 256>>>(fl_w, fl_b);
    deltas_k<<<6, 512>>>(dl_w, dl_b);
    // separable triline table
    gtable_k<<<576, 32>>>();
    // decoder
    decoder_k<<<3456, 256>>>(w1, b1, w2, b2, out);
}

// round 6
// speedup vs baseline: 1.0545x; 1.0545x over previous
#include <cuda_runtime.h>
#include <cstdint>

// ---------------------------------------------------------------------------
// TrilineVAE full pipeline (smem-tiled convs + smem-factorized decoder)
// ---------------------------------------------------------------------------

#define PRED_SIZE 1769472   // 2*96^3
#define HALF_PRED 884736    // 96^3

typedef unsigned long long ull;

__device__ __forceinline__ ull fma2(ull a, ull b, ull c) {
    ull r;
    asm("fma.rn.f32x2 %0,%1,%2,%3;" : "=l"(r) : "l"(a), "l"(b), "l"(c));
    return r;
}
__device__ __forceinline__ ull mul2(ull a, ull b) {
    ull r;
    asm("mul.rn.f32x2 %0,%1,%2;" : "=l"(r) : "l"(a), "l"(b));
    return r;
}
__device__ __forceinline__ void unpack2(ull v, float& lo, float& hi) {
    asm("mov.b64 {%0,%1},%2;" : "=f"(lo), "=f"(hi) : "l"(v));
}

// ---------------- scratch (__device__ globals; no allocation) --------------
__device__ __align__(16) float g_act0[2 * 32 * 48 * 48 * 48];   // 7,077,888
__device__ __align__(16) float g_act1[2 * 64 * 24 * 24 * 24];   // 1,769,472
__device__ __align__(16) float g_act2raw[4 * 2 * 128 * 1728];   // 1,769,472
__device__ __align__(16) float g_act2[2 * 128 * 1728];          //   442,368
__device__ __align__(16) float g_act3raw[8 * 2 * 256 * 216];    //   884,736
__device__ __align__(16) float g_act3[2 * 256 * 216];           //   110,592
__device__ __align__(16) float g_act4raw[16 * 2 * 512 * 27];    //   442,368
__device__ __align__(16) float g_xpad5[2 * 512 * 64];           //    65,536
__device__ __align__(16) float g_flat5[2 * 512];
__device__ __align__(16) float g_z[2 * 128];
__device__ __align__(16) float g_knots[6 * 512];
__device__ __align__(16) float g_feats[2 * 3 * 512 * 32];       //    98,304
__device__ __align__(16) float g_g[2 * 3 * 96 * 32];            //    18,432

// ---------------------------------------------------------------------------
// Tiled direct conv3d (k=4, s=2, p=1), packed-f32x2 inner loop.
// ---------------------------------------------------------------------------
template <int CIN, int COUT, int SIN, int SOUT, int TD, int TH, int TW,
          int OCB, int ICT, int ICSPLIT, int PT, int OCT, bool FUSE>
__global__ void convt_k(const float* __restrict__ in, const float* __restrict__ wt,
                        const float* __restrict__ bias, float* __restrict__ out) {
    constexpr int POS_TILE = TD * TH * TW;
    constexpr int NPOS_T = POS_TILE / PT;
    constexpr int NOC_T = OCB / OCT;
    constexpr int BLK = NPOS_T * NOC_T;
    constexpr int TD2 = 2 * TD + 2, TH2 = 2 * TH + 2, TW2 = 2 * TW + 2;
    constexpr int INEL = TD2 * TH2 * TW2;
    constexpr int POS_OUT = SOUT * SOUT * SOUT;
    constexpr int ICR = CIN / ICSPLIT;
    constexpr int NT_W = SOUT / TW, NT_H = SOUT / TH;

    __shared__ __align__(16) float sIn[ICT * INEL];
    __shared__ __align__(16) float sW[OCB * ICT * 64];

    const int tid = threadIdx.x;
    const int n = blockIdx.z;
    const int oc0 = blockIdx.y * OCB;
    int bx = blockIdx.x;
    const int sp = bx % ICSPLIT; bx /= ICSPLIT;
    const int twi = bx % NT_W; bx /= NT_W;
    const int thi = bx % NT_H; bx /= NT_H;
    const int tdi = bx;
    const int od0 = tdi * TD, oh0 = thi * TH, ow0 = twi * TW;
    const int id0 = 2 * od0 - 1, ih0 = 2 * oh0 - 1, iw0 = 2 * ow0 - 1;
    const int icBeg = sp * ICR;

    const int posT = tid % NPOS_T;
    const int ocT = tid / NPOS_T;

    int baseq[PT];
    int gpos[PT];
#pragma unroll
    for (int q = 0; q < PT; q++) {
        int p = posT + q * NPOS_T;
        int owl = p % TW;
        int ohl = (p / TW) % TH;
        int odl = p / (TW * TH);
        baseq[q] = (2 * odl) * TH2 * TW2 + (2 * ohl) * TW2 + 2 * owl;
        gpos[q] = ((od0 + odl) * SOUT + (oh0 + ohl)) * SOUT + (ow0 + owl);
    }

    ull acc2[PT * OCT];
#pragma unroll
    for (int i = 0; i < PT * OCT; i++) acc2[i] = 0ull;

    const float* inN = in + (size_t)n * CIN * SIN * SIN * SIN;

    for (int icc = 0; icc < ICR; icc += ICT) {
        __syncthreads();
        for (int e = tid; e < ICT * INEL; e += BLK) {
            int icl = e / INEL;
            int r = e % INEL;
            int dd = r / (TH2 * TW2);
            int hh = (r / TW2) % TH2;
            int ww = r % TW2;
            int id = id0 + dd, ih = ih0 + hh, iw = iw0 + ww;
            float v = 0.f;
            if ((unsigned)id < (unsigned)SIN && (unsigned)ih < (unsigned)SIN &&
                (unsigned)iw < (unsigned)SIN)
                v = __ldg(&inN[(((size_t)(icBeg + icc + icl) * SIN + id) * SIN + ih) * SIN + iw]);
            sIn[e] = v;
        }
        for (int e = tid; e < OCB * ICT * 64; e += BLK) {
            int o = e / (ICT * 64);
            int r = e % (ICT * 64);
            int icl = r / 64;
            int t = r % 64;
            sW[e] = __ldg(&wt[((size_t)(oc0 + o) * CIN + (icBeg + icc + icl)) * 64 + t]);
        }
        __syncthreads();

#pragma unroll
        for (int icl = 0; icl < ICT; icl++) {
            const float* inL = sIn + icl * INEL;
#pragma unroll
            for (int kd = 0; kd < 4; kd++) {
#pragma unroll
                for (int kh = 0; kh < 4; kh++) {
                    const float* row = inL + kd * TH2 * TW2 + kh * TW2;
                    ull xu[PT][2];
#pragma unroll
                    for (int q = 0; q < PT; q++) {
                        const ull* rp = reinterpret_cast<const ull*>(row + baseq[q]);
                        xu[q][0] = rp[0];
                        xu[q][1] = rp[1];
                    }
#pragma unroll
                    for (int j = 0; j < OCT; j++) {
                        const ull* wp = reinterpret_cast<const ull*>(
                            sW + ((ocT * OCT + j) * ICT + icl) * 64 + kd * 16 + kh * 4);
                        ull w0 = wp[0], w1 = wp[1];
#pragma unroll
                        for (int q = 0; q < PT; q++) {
                            ull a = acc2[q * OCT + j];
                            a = fma2(xu[q][0], w0, a);
                            a = fma2(xu[q][1], w1, a);
                            acc2[q * OCT + j] = a;
                        }
                    }
                }
            }
        }
    }

    if (FUSE) {
#pragma unroll
        for (int j = 0; j < OCT; j++) {
            int oc = oc0 + ocT * OCT + j;
            float bb = __ldg(&bias[oc]);
#pragma unroll
            for (int q = 0; q < PT; q++) {
                float lo, hi;
                unpack2(acc2[q * OCT + j], lo, hi);
                out[((size_t)n * COUT + oc) * POS_OUT + gpos[q]] =
                    fmaxf(lo + hi + bb, 0.f);
            }
        }
    } else {
        float* outS = out + (size_t)sp * (2ull * COUT * POS_OUT);
#pragma unroll
        for (int j = 0; j < OCT; j++) {
            int oc = oc0 + ocT * OCT + j;
#pragma unroll
            for (int q = 0; q < PT; q++) {
                float lo, hi;
                unpack2(acc2[q * OCT + j], lo, hi);
                outS[((size_t)n * COUT + oc) * POS_OUT + gpos[q]] = lo + hi;
            }
        }
    }
}

// generic slice reducer: sum NS slices + bias + relu
template <int NS, int TOTAL, int PP, int COUT>
__global__ void reduceN_k(const float* __restrict__ raw, const float* __restrict__ bias,
                          float* __restrict__ out) {
    int idx = blockIdx.x * 256 + threadIdx.x;
    if (idx >= TOTAL) return;
    float s = __ldg(&bias[(idx / PP) % COUT]);
#pragma unroll
    for (int q = 0; q < NS; q++) s += raw[(size_t)q * TOTAL + idx];
    out[idx] = fmaxf(s, 0.f);
}

// reduce conv4 slices + bias + relu into zero-padded im2col vector for conv5
__global__ void pad45_k(const float* __restrict__ b4) {
    int idx = blockIdx.x * 256 + threadIdx.x;  // < 65536
    int n = idx >> 15;
    int r = idx & 32767;
    int ic = r >> 6;
    int tt = r & 63;
    int kd = tt >> 4, kh = (tt >> 2) & 3, kw = tt & 3;
    float val = 0.f;
    if (kd >= 1 && kh >= 1 && kw >= 1) {
        int base = (n * 512 + ic) * 27 + (kd - 1) * 9 + (kh - 1) * 3 + (kw - 1);
        float s = __ldg(&b4[ic]);
#pragma unroll
        for (int q = 0; q < 16; q++) s += g_act4raw[q * 27648 + base];
        val = fmaxf(s, 0.f);
    }
    g_xpad5[idx] = val;
}

// conv5 as dot products: out[n,oc] = xpad[n] . W5[oc]  (K = 32768)
__global__ void conv5_k(const float* __restrict__ w5, const float* __restrict__ b5) {
    const int oc = blockIdx.x;
    const int t = threadIdx.x;
    const float* wr = w5 + (size_t)oc * 32768;
    ull a0 = 0ull, a1 = 0ull;
    for (int k = t * 4; k < 32768; k += 1024) {
        const ull* w = reinterpret_cast<const ull*>(wr + k);
        const ull* x0 = reinterpret_cast<const ull*>(g_xpad5 + k);
        const ull* x1 = reinterpret_cast<const ull*>(g_xpad5 + 32768 + k);
        ull w0 = w[0], w1 = w[1];
        a0 = fma2(w0, x0[0], a0); a0 = fma2(w1, x0[1], a0);
        a1 = fma2(w0, x1[0], a1); a1 = fma2(w1, x1[1], a1);
    }
    float l0, h0, l1, h1;
    unpack2(a0, l0, h0);
    unpack2(a1, l1, h1);
    float s0v = l0 + h0, s1v = l1 + h1;
    __shared__ float s0[8], s1[8];
    int lane = t & 31, wid = t >> 5;
#pragma unroll
    for (int off = 16; off; off >>= 1) {
        s0v += __shfl_down_sync(0xffffffffu, s0v, off);
        s1v += __shfl_down_sync(0xffffffffu, s1v, off);
    }
    if (lane == 0) { s0[wid] = s0v; s1[wid] = s1v; }
    __syncthreads();
    if (t == 0) {
        float r0 = 0.f, r1 = 0.f;
#pragma unroll
        for (int q = 0; q < 8; q++) { r0 += s0[q]; r1 += s1[q]; }
        float bb = __ldg(&b5[oc]);
        g_flat5[oc]       = fmaxf(r0 + bb, 0.f);
        g_flat5[512 + oc] = fmaxf(r1 + bb, 0.f);
    }
}

// fc -> stats -> mu/logvar -> z ; writes mu, logvar to d_out tail
__global__ void head1_k(const float* __restrict__ fc_w, const float* __restrict__ fc_b,
                        const float* __restrict__ eps, float* __restrict__ d_out) {
    __shared__ float fs[1024];
    __shared__ float stats[512];
    int t = threadIdx.x;  // 256
    for (int e = t; e < 1024; e += 256) fs[e] = g_flat5[e];
    __syncthreads();
    {
        float a0 = __ldg(&fc_b[t]), a1 = a0;
        for (int i = 0; i < 512; i++) {
            float w = __ldg(&fc_w[i * 256 + t]);
            a0 = fmaf(fs[i], w, a0);
            a1 = fmaf(fs[512 + i], w, a1);
        }
        stats[t] = a0;
        stats[256 + t] = a1;
    }
    __syncthreads();
    int n = t >> 7, jj = t & 127;
    float mu = stats[n * 256 + jj];
    float lv = stats[n * 256 + 128 + jj];
    g_z[t] = mu + __ldg(&eps[t]) * expf(0.5f * lv);
    d_out[PRED_SIZE + t] = mu;
    d_out[PRED_SIZE + 256 + t] = lv;
}

// feats = relu(z @ fl_w + fl_b) -> [2,3,512,32]; both batches per thread
__global__ void feats_k(const float* __restrict__ fl_w, const float* __restrict__ fl_b) {
    __shared__ float zs[256];
    int t = threadIdx.x;
    int gid = blockIdx.x * 256 + t;  // < 49152
    zs[t] = g_z[t];
    __syncthreads();
    float b = __ldg(&fl_b[gid]);
    float a0 = b, a1 = b;
#pragma unroll 4
    for (int i = 0; i < 128; i++) {
        float w = __ldg(&fl_w[(size_t)i * 49152 + gid]);
        a0 = fmaf(zs[i], w, a0);
        a1 = fmaf(zs[128 + i], w, a1);
    }
    g_feats[gid] = fmaxf(a0, 0.f);
    g_feats[49152 + gid] = fmaxf(a1, 0.f);
}

// deltas row -> softmax -> cumsum -> knots  (one block per (b,axis))
__global__ void deltas_k(const float* __restrict__ dl_w, const float* __restrict__ dl_b) {
    int b = blockIdx.x / 3, ax = blockIdx.x % 3;
    int t = threadIdx.x;  // 512
    __shared__ float zs[128];
    __shared__ float v[512];
    __shared__ float r[512];
    if (t < 128) zs[t] = g_z[b * 128 + t];
    __syncthreads();
    float val = -1e30f;
    if (t < 511) {
        float a = __ldg(&dl_b[ax * 511 + t]);
        for (int i = 0; i < 128; i++)
            a = fmaf(zs[i], __ldg(&dl_w[i * 1533 + ax * 511 + t]), a);
        val = a;
    }
    r[t] = val;
    __syncthreads();
    for (int s = 256; s > 0; s >>= 1) {
        if (t < s) r[t] = fmaxf(r[t], r[t + s]);
        __syncthreads();
    }
    float mx = r[0];
    __syncthreads();
    float e = (t < 511) ? expf(val - mx) : 0.f;
    r[t] = e;
    __syncthreads();
    for (int s = 256; s > 0; s >>= 1) {
        if (t < s) r[t] += r[t + s];
        __syncthreads();
    }
    float sum = r[0];
    __syncthreads();
    v[t] = e / sum;
    __syncthreads();
    for (int off = 1; off < 512; off <<= 1) {
        float x = v[t];
        float add = (t >= off) ? v[t - off] : 0.f;
        __syncthreads();
        v[t] = x + add;
        __syncthreads();
    }
    float* kr = g_knots + (b * 3 + ax) * 512;
    if (t == 0) kr[0] = 0.f;
    if (t < 511) kr[t + 1] = v[t];
}

// Separable triline table: one block (32 threads) per (b,axis,i).
__global__ void gtable_k() {
    int blk = blockIdx.x;  // 576
    int i = blk % 96;
    int ax = (blk / 96) % 3;
    int b = blk / 288;
    const float* kr = g_knots + (b * 3 + ax) * 512;
    float u = (i + 0.5f) * (1.0f / 96.0f);
    int lo = 0, hi = 512;
    while (lo < hi) {
        int mid = (lo + hi) >> 1;
        if (__ldg(&kr[mid]) <= u) lo = mid + 1; else hi = mid;
    }
    int idx = lo - 1;
    idx = max(0, min(idx, 510));
    float t0 = __ldg(&kr[idx]), t1 = __ldg(&kr[idx + 1]);
    float w = (u - t0) / (t1 - t0 + 1e-8f);
    w = fminf(fmaxf(w, 0.f), 1.f);
    int d = threadIdx.x;
    const float* fr = g_feats + (((b * 3 + ax) * 512) + idx) * 32;
    g_g[((b * 3 + ax) * 96 + i) * 32 + d] = fr[d] * (1.f - w) + fr[32 + d] * w;
}

// ---------------------------------------------------------------------------
// Decoder v2: block = (i, 4 j values, all 96 k), 384 threads.
// e = g0[i]⊙g1[j] computed once into smem; axis-2 table staged TRANSPOSED in
// smem ([d-pair][k], padded rows) so per-thread reads are conflict-free LDS;
// W1^T broadcast from smem. Packed fma2 GEMM with 4 independent acc chains.
// ---------------------------------------------------------------------------
__global__ __launch_bounds__(384) void decoder_k(
    const float* __restrict__ w1, const float* __restrict__ b1,
    const float* __restrict__ w2, const float* __restrict__ b2,
    float* __restrict__ out) {
    __shared__ __align__(16) ull sG2[2 * 16 * 97];   // [b][qd][k], row pad 97
    __shared__ __align__(16) float W1t[64 * 32];     // [kk][d]
    __shared__ __align__(16) float sE[2 * 4 * 32];   // [b][jl][d]
    __shared__ float b1s[64], w2s[64];

    const int t = threadIdx.x;
    const int i = blockIdx.x / 24;
    const int j0 = (blockIdx.x % 24) * 4;

    for (int e = t; e < 2048; e += 384) {
        int kk = e >> 5, d = e & 31;
        W1t[e] = __ldg(&w1[d * 64 + kk]);
    }
    if (t < 64) { b1s[t] = __ldg(&b1[t]); w2s[t] = __ldg(&w2[t]); }
    // stage g2 transposed: src linear r = k*16 + qd (coalesced LDG), dst [qd][k]
    for (int e = t; e < 2 * 1536; e += 384) {
        int b = e / 1536, r = e % 1536;
        int k = r / 16, qd = r % 16;
        const ull* src = reinterpret_cast<const ull*>(g_g + b * 9216 + 6144);
        sG2[b * 1552 + qd * 97 + k] = src[r];
    }
    if (t < 256) {
        int b = t >> 7, jl = (t >> 5) & 3, d = t & 31;
        float v0 = g_g[b * 9216 + i * 32 + d];
        float v1 = g_g[b * 9216 + (96 + j0 + jl) * 32 + d];
        sE[(b * 4 + jl) * 32 + d] = v0 * v1;
    }
    __syncthreads();

    const int jl = t / 96;
    const int k = t % 96;
    const ull* ea = reinterpret_cast<const ull*>(sE + jl * 32);
    const ull* eb = reinterpret_cast<const ull*>(sE + (4 + jl) * 32);

    ull fa[16], fb[16];
#pragma unroll
    for (int q = 0; q < 16; q++) {
        fa[q] = mul2(ea[q], sG2[q * 97 + k]);
        fb[q] = mul2(eb[q], sG2[1552 + q * 97 + k]);
    }

    float bv = __ldg(b2);
    float la = bv, lb = bv;
#pragma unroll 2
    for (int kk = 0; kk < 64; kk++) {
        const ulonglong2* wp = reinterpret_cast<const ulonglong2*>(W1t + kk * 32);
        ull a0 = 0ull, a1 = 0ull, c0 = 0ull, c1 = 0ull;
#pragma unroll
        for (int q = 0; q < 8; q++) {
            ulonglong2 w = wp[q];
            a0 = fma2(fa[2 * q + 0], w.x, a0);
            a1 = fma2(fa[2 * q + 1], w.y, a1);
            c0 = fma2(fb[2 * q + 0], w.x, c0);
            c1 = fma2(fb[2 * q + 1], w.y, c1);
        }
        float x0, x1, x2, x3, y0, y1, y2, y3;
        unpack2(a0, x0, x1); unpack2(a1, x2, x3);
        unpack2(c0, y0, y1); unpack2(c1, y2, y3);
        la = fmaf(fmaxf((x0 + x1) + (x2 + x3) + b1s[kk], 0.f), w2s[kk], la);
        lb = fmaf(fmaxf((y0 + y1) + (y2 + y3) + b1s[kk], 0.f), w2s[kk], lb);
    }
    int p = (i * 96 + j0 + jl) * 96 + k;
    out[p] = la;
    out[HALF_PRED + p] = lb;
}

// ---------------------------------------------------------------------------
extern "C" void kernel_launch(void* const* d_in, const int* in_sizes, int n_in,
                              void* d_out, int out_size) {
    const float* occ  = (const float*)d_in[0];
    const float* eps  = (const float*)d_in[1];
    const float* cw0  = (const float*)d_in[3];
    const float* cb0  = (const float*)d_in[4];
    const float* cw1  = (const float*)d_in[5];
    const float* cb1  = (const float*)d_in[6];
    const float* cw2  = (const float*)d_in[7];
    const float* cb2  = (const float*)d_in[8];
    const float* cw3  = (const float*)d_in[9];
    const float* cb3  = (const float*)d_in[10];
    const float* cw4  = (const float*)d_in[11];
    const float* cb4  = (const float*)d_in[12];
    const float* cw5  = (const float*)d_in[13];
    const float* cb5  = (const float*)d_in[14];
    const float* fc_w = (const float*)d_in[15];
    const float* fc_b = (const float*)d_in[16];
    const float* dl_w = (const float*)d_in[17];
    const float* dl_b = (const float*)d_in[18];
    const float* fl_w = (const float*)d_in[19];
    const float* fl_b = (const float*)d_in[20];
    const float* w1   = (const float*)d_in[21];
    const float* b1   = (const float*)d_in[22];
    const float* w2   = (const float*)d_in[23];
    const float* b2   = (const float*)d_in[24];
    float* out = (float*)d_out;

    float *a0p, *a1p, *a2rp, *a2p, *a3rp, *a3p, *a4rp;
    cudaGetSymbolAddress((void**)&a0p, g_act0);
    cudaGetSymbolAddress((void**)&a1p, g_act1);
    cudaGetSymbolAddress((void**)&a2rp, g_act2raw);
    cudaGetSymbolAddress((void**)&a2p, g_act2);
    cudaGetSymbolAddress((void**)&a3rp, g_act3raw);
    cudaGetSymbolAddress((void**)&a3p, g_act3);
    cudaGetSymbolAddress((void**)&a4rp, g_act4raw);

    // conv0: 1->32, 96->48
    convt_k<1, 32, 96, 48, 8, 8, 8, 16, 1, 1, 4, 8, true>
        <<<dim3(216, 2, 2), 256>>>(occ, cw0, cb0, a0p);
    // conv1: 32->64, 48->24
    convt_k<32, 64, 48, 24, 4, 8, 8, 16, 2, 1, 4, 8, true>
        <<<dim3(54, 4, 2), 128>>>(a0p, cw1, cb1, a1p);
    // conv2: 64->128, 24->12, ICSPLIT4
    convt_k<64, 128, 24, 12, 6, 6, 12, 16, 1, 4, 4, 8, false>
        <<<dim3(16, 8, 2), 216>>>(a1p, cw2, cb2, a2rp);
    reduceN_k<4, 442368, 1728, 128><<<1728, 256>>>(a2rp, cb2, a2p);
    // conv3: 128->256, 12->6, ICSPLIT8
    convt_k<128, 256, 12, 6, 6, 6, 6, 32, 2, 8, 4, 8, false>
        <<<dim3(8, 8, 2), 216>>>(a2p, cw3, cb3, a3rp);
    reduceN_k<8, 110592, 216, 256><<<432, 256>>>(a3rp, cb3, a3p);
    // conv4: 256->512, 6->3, ICSPLIT16
    convt_k<256, 512, 6, 3, 3, 3, 3, 32, 4, 16, 1, 8, false>
        <<<dim3(16, 16, 2), 108>>>(a3p, cw4, cb4, a4rp);
    pad45_k<<<256, 256>>>(cb4);
    // conv5: 512->512, 3->1 (padded dot-product)
    conv5_k<<<512, 256>>>(cw5, cb5);
    // fc / reparam / mu,logvar out
    head1_k<<<1, 256>>>(fc_w, fc_b, eps, out);
    // feature lines + knots
    feats_k<<<192, 256>>>(fl_w, fl_b);
    deltas_k<<<6, 512>>>(dl_w, dl_b);
    // separable triline table
    gtable_k<<<576, 32>>>();
    // decoder v2
    decoder_k<<<2304, 384>>>(w1, b1, w2, b2, out);
}